// round 12
// baseline (speedup 1.0000x reference)
#include <cuda_runtime.h>
#include <cuda_fp16.h>
#include <cstdint>

#define BB 32
#define AA 1024
#define DD 384
#define EE 4
#define H1C 256
#define H2C 192
#define NATOMS (BB*AA)
#define TM 128
#define NT 512
#define MAXTILES 260

// ---- dynamic SMEM byte map (per CTA) ----
#define A_CHK 10240
#define H1_OFF 122880
#define H1_CHK 8192
#define DSMEM 188416

// fragment-pair weights: [e][kc2][pair][lane] as uint4 {b0a,b1a,b0b,b1b}
#define W1F4_N (EE * 24 * 16 * 32)   // 49152
#define WHF4_N (EE * 16 * 12 * 32)   // 24576

// ---------------- device scratch ----------------
__device__ int   g_counts[EE];
__device__ int   g_perm[EE * NATOMS];
__device__ __align__(16) uint4 g_W1f4[W1F4_N];
__device__ __align__(16) uint4 g_Whf4[WHF4_N];

// ---------------- helpers ----------------
__device__ __forceinline__ uint32_t s2u(const void* p) {
    uint32_t a;
    asm("{ .reg .u64 t; cvta.to.shared.u64 t, %1; cvt.u32.u64 %0, t; }" : "=r"(a) : "l"(p));
    return a;
}

__device__ __forceinline__ uint32_t pack2h(float x0, float x1) {
    __half2 h = __floats2half2_rn(x0, x1);
    return *(uint32_t*)&h;
}

__device__ __forceinline__ void mma_f16(float* d,
        const uint32_t* a, uint32_t b0, uint32_t b1) {
    asm volatile(
        "mma.sync.aligned.m16n8k16.row.col.f32.f16.f16.f32 "
        "{%0,%1,%2,%3}, {%4,%5,%6,%7}, {%8,%9}, {%0,%1,%2,%3};"
        : "+f"(d[0]), "+f"(d[1]), "+f"(d[2]), "+f"(d[3])
        : "r"(a[0]), "r"(a[1]), "r"(a[2]), "r"(a[3]), "r"(b0), "r"(b1));
}

__device__ __forceinline__ void ldm4(uint32_t* r, uint32_t addr) {
    asm volatile("ldmatrix.sync.aligned.m8n8.x4.shared.b16 {%0,%1,%2,%3}, [%4];"
        : "=r"(r[0]), "=r"(r[1]), "=r"(r[2]), "=r"(r[3]) : "r"(addr));
}

// ---------------- setup: bucket (blocks 0..127) + fragment prep ----------------
__global__ void bucket_prep_kernel(const int* __restrict__ species,
                                   const float* __restrict__ W1,
                                   const float* __restrict__ Wh) {
    const int tid = threadIdx.x;
    const int b = blockIdx.x;
    if (b < 128) {
        int i = b * 256 + tid;
        int lane = tid & 31;
        int e = species[i];
        unsigned mask = __match_any_sync(0xffffffffu, e);
        int leader = __ffs(mask) - 1;
        int rank = __popc(mask & ((1u << lane) - 1u));
        int base = 0;
        if (lane == leader) base = atomicAdd(&g_counts[e], __popc(mask));
        base = __shfl_sync(0xffffffffu, base, leader);
        g_perm[e * NATOMS + base + rank] = i;
        return;
    }
    int idx = (b - 128) * 256 + tid;
    if (idx < W1F4_N) {
        int lane = idx & 31;
        int p8   = (idx >> 5) & 15;
        int rest = idx >> 9;
        int kc2  = rest % 24;
        int e    = rest / 24;
        int k = kc2 * 16 + 2 * (lane & 3);
        int n = p8 * 16 + (lane >> 2);
        const float* Wp = W1 + ((size_t)e * DD + k) * H1C + n;
        uint32_t b0a = pack2h(Wp[0],                Wp[H1C]);
        uint32_t b1a = pack2h(Wp[(size_t)8 * H1C],  Wp[(size_t)9 * H1C]);
        uint32_t b0b = pack2h(Wp[8],                Wp[H1C + 8]);
        uint32_t b1b = pack2h(Wp[(size_t)8 * H1C + 8], Wp[(size_t)9 * H1C + 8]);
        g_W1f4[idx] = make_uint4(b0a, b1a, b0b, b1b);
    } else if (idx < W1F4_N + WHF4_N) {
        int i2 = idx - W1F4_N;
        int lane = i2 & 31;
        int tmp  = i2 >> 5;
        int p8   = tmp % 12;
        int rest = tmp / 12;
        int kc2  = rest % 16;
        int e    = rest / 16;
        int k = kc2 * 16 + 2 * (lane & 3);
        int n = p8 * 16 + (lane >> 2);
        const float* Wp = Wh + ((size_t)e * H1C + k) * H2C + n;
        uint32_t b0a = pack2h(Wp[0],                Wp[H2C]);
        uint32_t b1a = pack2h(Wp[(size_t)8 * H2C],  Wp[(size_t)9 * H2C]);
        uint32_t b0b = pack2h(Wp[8],                Wp[H2C + 8]);
        uint32_t b1b = pack2h(Wp[(size_t)8 * H2C + 8], Wp[(size_t)9 * H2C + 8]);
        g_Whf4[i2] = make_uint4(b0a, b1a, b0b, b1b);
    }
}

// ---------------- fused 2-layer MLP + batch reduction ----------------
__global__ void __launch_bounds__(NT, 1) fused_mlp(
    const float* __restrict__ rep,
    const float* __restrict__ b1, const float* __restrict__ bh,
    const float* __restrict__ W2, const float* __restrict__ b2,
    float* __restrict__ outp)
{
    extern __shared__ __align__(16) char dsm[];
    __shared__ int   prow[TM];
    __shared__ float b1s[H1C];
    __shared__ float bhs[H2C];
    __shared__ float w2s[H2C];
    __shared__ float red[TM][4];
    __shared__ float bins[BB];

    const int tid  = threadIdx.x;
    const int w    = tid >> 5;
    const int lane = tid & 31;
    const int g    = lane >> 2;
    const int t    = lane & 3;
    const int llow = lane & 15;
    const int ahi16 = (lane >> 4) << 4;

    const int wm1 = w >> 3;        // 0..1 -> 64-row slab
    const int wn1 = w & 7;         // 0..7 -> 32-col strip
    const int wm2 = w >> 2;        // 0..3 -> 32-row slab
    const int wn2 = w & 3;         // 0..3 -> 48-col strip

    int c0 = g_counts[0], c1 = g_counts[1], c2 = g_counts[2], c3 = g_counts[3];
    int t0 = (c0 + TM - 1) / TM, t1 = (c1 + TM - 1) / TM;
    int t2 = (c2 + TM - 1) / TM, t3 = (c3 + TM - 1) / TM;
    int bid = blockIdx.x, e, tloc, cnt;
    if      (bid < t0)                { e = 0; tloc = bid;                cnt = c0; }
    else if (bid < t0 + t1)           { e = 1; tloc = bid - t0;           cnt = c1; }
    else if (bid < t0 + t1 + t2)      { e = 2; tloc = bid - t0 - t1;      cnt = c2; }
    else if (bid < t0 + t1 + t2 + t3) { e = 3; tloc = bid - t0 - t1 - t2; cnt = c3; }
    else return;

    const int row0   = tloc * TM;
    const int mcount = min(TM, cnt - row0);
    if (tid < TM)
        prow[tid] = (tid < mcount) ? g_perm[e * NATOMS + row0 + tid] : -1;
    if (tid < H1C) b1s[tid] = b1[e * H1C + tid];
    if (tid < H2C) { bhs[tid] = bh[e * H2C + tid]; w2s[tid] = W2[e * H2C + tid]; }
    if (tid < BB) bins[tid] = 0.f;
    __syncthreads();

    const uint32_t sb = s2u(dsm);

    // ---- pack FULL A tile (128 x 384) fp16 into chunked smem, once ----
    {
        int r = tid >> 2;
        int fq = tid & 3;
        int p = prow[r];
        const float4* src = (p >= 0) ? (const float4*)(rep + (size_t)p * DD) : nullptr;
        char* Arow = dsm + r * 80;
        #pragma unroll 3
        for (int c = 0; c < 12; c++) {
            #pragma unroll
            for (int j = 0; j < 2; j++) {
                int f = fq * 2 + j;
                float4 v = src ? __ldg(src + c * 8 + f) : make_float4(0.f, 0.f, 0.f, 0.f);
                *(uint2*)(Arow + c * A_CHK + f * 8) =
                    make_uint2(pack2h(v.x, v.y), pack2h(v.z, v.w));
            }
        }
    }
    __syncthreads();

    // ================== LAYER 1: D1[128x256] = A @ W1[e]^T (sync-free) ==================
    const uint32_t aB1 = sb + (uint32_t)((wm1 * 64 + llow) * 80 + ahi16);
    const uint4* __restrict__ w1f = g_W1f4 + ((size_t)(e * 24) * 16 + wn1 * 2) * 32 + lane;

    float acc[4][4][4];
    #pragma unroll
    for (int mt = 0; mt < 4; mt++)
        #pragma unroll
        for (int nt = 0; nt < 4; nt++)
            #pragma unroll
            for (int q = 0; q < 4; q++) acc[mt][nt][q] = 0.f;

    uint4 nb0 = __ldg(w1f);
    uint4 nb1 = __ldg(w1f + 32);
    #pragma unroll 2
    for (int kc2 = 0; kc2 < 24; kc2++) {
        uint4 b01 = nb0, b23 = nb1;
        if (kc2 + 1 < 24) {
            nb0 = __ldg(w1f + (kc2 + 1) * 512);
            nb1 = __ldg(w1f + (kc2 + 1) * 512 + 32);
        }
        const uint32_t aB = aB1 + (kc2 >> 1) * A_CHK + (kc2 & 1) * 32;
        uint32_t af[4][4];
        ldm4(af[0], aB);
        ldm4(af[1], aB + 1280);
        ldm4(af[2], aB + 2560);
        ldm4(af[3], aB + 3840);
        #pragma unroll
        for (int mt = 0; mt < 4; mt++) {
            mma_f16(acc[mt][0], af[mt], b01.x, b01.y);
            mma_f16(acc[mt][1], af[mt], b01.z, b01.w);
            mma_f16(acc[mt][2], af[mt], b23.x, b23.y);
            mma_f16(acc[mt][3], af[mt], b23.z, b23.w);
        }
    }

    // ---- H1 = D1 + b1 (NO relu — reference quirk) -> chunked swizzled smem ----
    {
        char* Hh = dsm + H1_OFF;
        #pragma unroll
        for (int mt = 0; mt < 4; mt++) {
            #pragma unroll
            for (int nt = 0; nt < 4; nt++) {
                int kin = nt * 8 + 2 * t;
                int c0i = wn1 * 32 + kin;
                int r0 = wm1 * 64 + mt * 16 + g, r1 = r0 + 8;
                uint32_t o0 = wn1 * H1_CHK + r0 * 64 + ((kin * 2) ^ ((r0 & 3) << 4));
                *(uint32_t*)(Hh + o0) =
                    pack2h(acc[mt][nt][0] + b1s[c0i], acc[mt][nt][1] + b1s[c0i + 1]);
                uint32_t o1 = wn1 * H1_CHK + r1 * 64 + ((kin * 2) ^ ((r1 & 3) << 4));
                *(uint32_t*)(Hh + o1) =
                    pack2h(acc[mt][nt][2] + b1s[c0i], acc[mt][nt][3] + b1s[c0i + 1]);
            }
        }
    }
    __syncthreads();

    // ================== LAYER 2: D2[128x192] = H1 @ Wh[e]^T (sync-free) ==================
    const uint32_t h1row2 = (uint32_t)(wm2 * 32 + llow);
    const uint32_t h1sw2  = (h1row2 & 3) << 4;
    const uint32_t aH2    = sb + H1_OFF + h1row2 * 64;
    const uint4* __restrict__ whf = g_Whf4 + ((size_t)(e * 16) * 12 + wn2 * 3) * 32 + lane;

    float acc2[2][6][4];
    #pragma unroll
    for (int mt = 0; mt < 2; mt++)
        #pragma unroll
        for (int nt = 0; nt < 6; nt++)
            #pragma unroll
            for (int q = 0; q < 4; q++) acc2[mt][nt][q] = 0.f;

    uint4 wb0 = __ldg(whf);
    uint4 wb1 = __ldg(whf + 32);
    uint4 wb2 = __ldg(whf + 64);
    #pragma unroll 2
    for (int kc2 = 0; kc2 < 16; kc2++) {
        uint4 p0 = wb0, p1 = wb1, p2 = wb2;
        if (kc2 + 1 < 16) {
            wb0 = __ldg(whf + (kc2 + 1) * 384);
            wb1 = __ldg(whf + (kc2 + 1) * 384 + 32);
            wb2 = __ldg(whf + (kc2 + 1) * 384 + 64);
        }
        const uint32_t colsw = (((kc2 & 1) << 5) + ahi16) ^ h1sw2;
        const uint32_t aH = aH2 + (kc2 >> 1) * H1_CHK + colsw;
        uint32_t ah0[4], ah1[4];
        ldm4(ah0, aH);
        ldm4(ah1, aH + 1024);
        mma_f16(acc2[0][0], ah0, p0.x, p0.y);
        mma_f16(acc2[1][0], ah1, p0.x, p0.y);
        mma_f16(acc2[0][1], ah0, p0.z, p0.w);
        mma_f16(acc2[1][1], ah1, p0.z, p0.w);
        mma_f16(acc2[0][2], ah0, p1.x, p1.y);
        mma_f16(acc2[1][2], ah1, p1.x, p1.y);
        mma_f16(acc2[0][3], ah0, p1.z, p1.w);
        mma_f16(acc2[1][3], ah1, p1.z, p1.w);
        mma_f16(acc2[0][4], ah0, p2.x, p2.y);
        mma_f16(acc2[1][4], ah1, p2.x, p2.y);
        mma_f16(acc2[0][5], ah0, p2.z, p2.w);
        mma_f16(acc2[1][5], ah1, p2.z, p2.w);
    }

    // ---- fused epilogue: E = relu(D2 + bh) . W2 + b2, per-batch bins ----
    {
        const int C0 = wn2 * 48;
        const int R0 = wm2 * 32;
        float pv[2][2] = {{0.f, 0.f}, {0.f, 0.f}};
        #pragma unroll
        for (int mt = 0; mt < 2; mt++) {
            #pragma unroll
            for (int nt = 0; nt < 6; nt++) {
                int c0i = C0 + nt * 8 + 2 * t;
                float bb0 = bhs[c0i],     w0 = w2s[c0i];
                float bb1 = bhs[c0i + 1], w1v = w2s[c0i + 1];
                float v;
                v = acc2[mt][nt][0] + bb0; v = v > 0.f ? v : 0.f; pv[mt][0] = fmaf(v, w0,  pv[mt][0]);
                v = acc2[mt][nt][1] + bb1; v = v > 0.f ? v : 0.f; pv[mt][0] = fmaf(v, w1v, pv[mt][0]);
                v = acc2[mt][nt][2] + bb0; v = v > 0.f ? v : 0.f; pv[mt][1] = fmaf(v, w0,  pv[mt][1]);
                v = acc2[mt][nt][3] + bb1; v = v > 0.f ? v : 0.f; pv[mt][1] = fmaf(v, w1v, pv[mt][1]);
            }
        }
        #pragma unroll
        for (int mt = 0; mt < 2; mt++) {
            #pragma unroll
            for (int h = 0; h < 2; h++) {
                pv[mt][h] += __shfl_xor_sync(0xffffffffu, pv[mt][h], 1);
                pv[mt][h] += __shfl_xor_sync(0xffffffffu, pv[mt][h], 2);
            }
        }
        if (t == 0) {
            #pragma unroll
            for (int mt = 0; mt < 2; mt++) {
                red[R0 + mt * 16 + g][wn2]     = pv[mt][0];
                red[R0 + mt * 16 + 8 + g][wn2] = pv[mt][1];
            }
        }
        __syncthreads();
        if (tid < TM) {
            int pr = prow[tid];
            if (pr >= 0) {
                float en = red[tid][0] + red[tid][1] + red[tid][2] + red[tid][3] + b2[e];
                atomicAdd(&bins[pr >> 10], en);
            }
        }
        __syncthreads();
        if (tid < BB) {
            float v = bins[tid];
            if (v != 0.f) atomicAdd(&outp[tid], v);
        }
    }
}

extern "C" void kernel_launch(void* const* d_in, const int* in_sizes, int n_in,
                              void* d_out, int out_size) {
    const float* rep     = (const float*)d_in[0];
    const int*   species = (const int*)  d_in[1];
    const float* W1      = (const float*)d_in[2];
    const float* b1      = (const float*)d_in[3];
    const float* Wh      = (const float*)d_in[4];
    const float* bh      = (const float*)d_in[5];
    const float* W2      = (const float*)d_in[6];
    const float* b2      = (const float*)d_in[7];
    float* out = (float*)d_out;

    cudaFuncSetAttribute(fused_mlp,
                         cudaFuncAttributeMaxDynamicSharedMemorySize, DSMEM);

    void* cptr = nullptr;
    cudaGetSymbolAddress(&cptr, g_counts);
    cudaMemsetAsync(cptr, 0, EE * sizeof(int), 0);
    cudaMemsetAsync(out, 0, BB * sizeof(float), 0);
    const int FRAG = W1F4_N + WHF4_N;               // 73728
    bucket_prep_kernel<<<128 + (FRAG + 255) / 256, 256>>>(species, W1, Wh);
    fused_mlp<<<MAXTILES, NT, DSMEM>>>(rep, b1, bh, W2, b2, out);
}

// round 13
// speedup vs baseline: 1.0633x; 1.0633x over previous
#include <cuda_runtime.h>
#include <cuda_fp16.h>
#include <cstdint>

#define BB 32
#define AA 1024
#define DD 384
#define EE 4
#define H1C 256
#define H2C 192
#define NATOMS (BB*AA)
#define TM 64
#define NT 256
#define MAXTILES 516

// ---- dynamic SMEM byte map (per CTA) ----
#define A_CHK 5120           // 64 rows x 80B per k32 chunk
#define H1_OFF 61440
#define H1_CHK 4096          // 64 rows x 64B per k32 chunk
#define DSMEM 94208

// fragment-pair weights: [e][kc2][pair][lane] as uint4 {b0a,b1a,b0b,b1b}
#define W1F4_N (EE * 24 * 16 * 32)   // 49152
#define WHF4_N (EE * 16 * 12 * 32)   // 24576

// ---------------- device scratch ----------------
__device__ int   g_counts[EE];
__device__ int   g_perm[EE * NATOMS];
__device__ __align__(16) uint4 g_W1f4[W1F4_N];
__device__ __align__(16) uint4 g_Whf4[WHF4_N];

// ---------------- helpers ----------------
__device__ __forceinline__ uint32_t s2u(const void* p) {
    uint32_t a;
    asm("{ .reg .u64 t; cvta.to.shared.u64 t, %1; cvt.u32.u64 %0, t; }" : "=r"(a) : "l"(p));
    return a;
}

__device__ __forceinline__ uint32_t pack2h(float x0, float x1) {
    __half2 h = __floats2half2_rn(x0, x1);
    return *(uint32_t*)&h;
}

__device__ __forceinline__ void mma_f16(float* d,
        const uint32_t* a, uint32_t b0, uint32_t b1) {
    asm volatile(
        "mma.sync.aligned.m16n8k16.row.col.f32.f16.f16.f32 "
        "{%0,%1,%2,%3}, {%4,%5,%6,%7}, {%8,%9}, {%0,%1,%2,%3};"
        : "+f"(d[0]), "+f"(d[1]), "+f"(d[2]), "+f"(d[3])
        : "r"(a[0]), "r"(a[1]), "r"(a[2]), "r"(a[3]), "r"(b0), "r"(b1));
}

__device__ __forceinline__ void ldm4(uint32_t* r, uint32_t addr) {
    asm volatile("ldmatrix.sync.aligned.m8n8.x4.shared.b16 {%0,%1,%2,%3}, [%4];"
        : "=r"(r[0]), "=r"(r[1]), "=r"(r[2]), "=r"(r[3]) : "r"(addr));
}

// ---------------- setup: bucket (blocks 0..127) + fragment prep ----------------
__global__ void bucket_prep_kernel(const int* __restrict__ species,
                                   const float* __restrict__ W1,
                                   const float* __restrict__ Wh) {
    const int tid = threadIdx.x;
    const int b = blockIdx.x;
    if (b < 128) {
        int i = b * 256 + tid;
        int lane = tid & 31;
        int e = species[i];
        unsigned mask = __match_any_sync(0xffffffffu, e);
        int leader = __ffs(mask) - 1;
        int rank = __popc(mask & ((1u << lane) - 1u));
        int base = 0;
        if (lane == leader) base = atomicAdd(&g_counts[e], __popc(mask));
        base = __shfl_sync(0xffffffffu, base, leader);
        g_perm[e * NATOMS + base + rank] = i;
        return;
    }
    int idx = (b - 128) * 256 + tid;
    if (idx < W1F4_N) {
        int lane = idx & 31;
        int p8   = (idx >> 5) & 15;
        int rest = idx >> 9;
        int kc2  = rest % 24;
        int e    = rest / 24;
        int k = kc2 * 16 + 2 * (lane & 3);
        int n = p8 * 16 + (lane >> 2);
        const float* Wp = W1 + ((size_t)e * DD + k) * H1C + n;
        uint32_t b0a = pack2h(Wp[0],                Wp[H1C]);
        uint32_t b1a = pack2h(Wp[(size_t)8 * H1C],  Wp[(size_t)9 * H1C]);
        uint32_t b0b = pack2h(Wp[8],                Wp[H1C + 8]);
        uint32_t b1b = pack2h(Wp[(size_t)8 * H1C + 8], Wp[(size_t)9 * H1C + 8]);
        g_W1f4[idx] = make_uint4(b0a, b1a, b0b, b1b);
    } else if (idx < W1F4_N + WHF4_N) {
        int i2 = idx - W1F4_N;
        int lane = i2 & 31;
        int tmp  = i2 >> 5;
        int p8   = tmp % 12;
        int rest = tmp / 12;
        int kc2  = rest % 16;
        int e    = rest / 16;
        int k = kc2 * 16 + 2 * (lane & 3);
        int n = p8 * 16 + (lane >> 2);
        const float* Wp = Wh + ((size_t)e * H1C + k) * H2C + n;
        uint32_t b0a = pack2h(Wp[0],                Wp[H2C]);
        uint32_t b1a = pack2h(Wp[(size_t)8 * H2C],  Wp[(size_t)9 * H2C]);
        uint32_t b0b = pack2h(Wp[8],                Wp[H2C + 8]);
        uint32_t b1b = pack2h(Wp[(size_t)8 * H2C + 8], Wp[(size_t)9 * H2C + 8]);
        g_Whf4[i2] = make_uint4(b0a, b1a, b0b, b1b);
    }
}

// ---------------- fused 2-layer MLP + batch reduction (TM=64, 2 CTA/SM) ----------------
__global__ void __launch_bounds__(NT, 2) fused_mlp(
    const float* __restrict__ rep,
    const float* __restrict__ b1, const float* __restrict__ bh,
    const float* __restrict__ W2, const float* __restrict__ b2,
    float* __restrict__ outp)
{
    extern __shared__ __align__(16) char dsm[];
    __shared__ int   prow[TM];
    __shared__ float b1s[H1C];
    __shared__ float bhs[H2C];
    __shared__ float w2s[H2C];
    __shared__ float red[TM][4];
    __shared__ float bins[BB];

    const int tid  = threadIdx.x;
    const int w    = tid >> 5;
    const int lane = tid & 31;
    const int g    = lane >> 2;
    const int t    = lane & 3;
    const int llow = lane & 15;
    const int ahi16 = (lane >> 4) << 4;

    const int wm = w >> 2;        // 0..1 -> 32-row slab (both layers)
    const int wn = w & 3;         // 0..3 -> N quarter

    int c0 = g_counts[0], c1 = g_counts[1], c2 = g_counts[2], c3 = g_counts[3];
    int t0 = (c0 + TM - 1) / TM, t1 = (c1 + TM - 1) / TM;
    int t2 = (c2 + TM - 1) / TM, t3 = (c3 + TM - 1) / TM;
    int bid = blockIdx.x, e, tloc, cnt;
    if      (bid < t0)                { e = 0; tloc = bid;                cnt = c0; }
    else if (bid < t0 + t1)           { e = 1; tloc = bid - t0;           cnt = c1; }
    else if (bid < t0 + t1 + t2)      { e = 2; tloc = bid - t0 - t1;      cnt = c2; }
    else if (bid < t0 + t1 + t2 + t3) { e = 3; tloc = bid - t0 - t1 - t2; cnt = c3; }
    else return;

    const int row0   = tloc * TM;
    const int mcount = min(TM, cnt - row0);
    if (tid < TM)
        prow[tid] = (tid < mcount) ? g_perm[e * NATOMS + row0 + tid] : -1;
    b1s[tid] = b1[e * H1C + tid];
    if (tid < H2C) { bhs[tid] = bh[e * H2C + tid]; w2s[tid] = W2[e * H2C + tid]; }
    if (tid < BB) bins[tid] = 0.f;
    __syncthreads();

    const uint32_t sb = s2u(dsm);

    // ---- pack FULL A tile (64 x 384) fp16 into chunked smem, once ----
    {
        int r = tid >> 2;             // 64 rows, 4 threads per row
        int fq = tid & 3;
        int p = prow[r];
        const float4* src = (p >= 0) ? (const float4*)(rep + (size_t)p * DD) : nullptr;
        char* Arow = dsm + r * 80;
        #pragma unroll 3
        for (int c = 0; c < 12; c++) {
            #pragma unroll
            for (int j = 0; j < 2; j++) {
                int f = fq * 2 + j;
                float4 v = src ? __ldg(src + c * 8 + f) : make_float4(0.f, 0.f, 0.f, 0.f);
                *(uint2*)(Arow + c * A_CHK + f * 8) =
                    make_uint2(pack2h(v.x, v.y), pack2h(v.z, v.w));
            }
        }
    }
    __syncthreads();

    // ================== LAYER 1: D1[64x256] = A @ W1[e]^T (sync-free) ==================
    const uint32_t aB1 = sb + (uint32_t)((wm * 32 + llow) * 80 + ahi16);
    const uint4* __restrict__ w1f = g_W1f4 + ((size_t)(e * 24) * 16 + wn * 4) * 32 + lane;

    float acc[2][8][4];
    #pragma unroll
    for (int mt = 0; mt < 2; mt++)
        #pragma unroll
        for (int nt = 0; nt < 8; nt++)
            #pragma unroll
            for (int q = 0; q < 4; q++) acc[mt][nt][q] = 0.f;

    uint4 nb[4];
    #pragma unroll
    for (int j = 0; j < 4; j++) nb[j] = __ldg(w1f + j * 32);
    #pragma unroll 2
    for (int kc2 = 0; kc2 < 24; kc2++) {
        uint4 bp[4];
        #pragma unroll
        for (int j = 0; j < 4; j++) bp[j] = nb[j];
        if (kc2 + 1 < 24) {
            #pragma unroll
            for (int j = 0; j < 4; j++)
                nb[j] = __ldg(w1f + (kc2 + 1) * 512 + j * 32);
        }
        const uint32_t aB = aB1 + (kc2 >> 1) * A_CHK + (kc2 & 1) * 32;
        uint32_t af[2][4];
        ldm4(af[0], aB);
        ldm4(af[1], aB + 1280);
        #pragma unroll
        for (int j = 0; j < 4; j++) {
            #pragma unroll
            for (int mt = 0; mt < 2; mt++) {
                mma_f16(acc[mt][2 * j],     af[mt], bp[j].x, bp[j].y);
                mma_f16(acc[mt][2 * j + 1], af[mt], bp[j].z, bp[j].w);
            }
        }
    }

    // ---- H1 = D1 + b1 (NO relu — reference quirk) -> chunked swizzled smem ----
    {
        char* Hh = dsm + H1_OFF;
        #pragma unroll
        for (int mt = 0; mt < 2; mt++) {
            #pragma unroll
            for (int nt = 0; nt < 8; nt++) {
                int c0i = wn * 64 + nt * 8 + 2 * t;
                int chunk = c0i >> 5, kin = c0i & 31;
                int r0 = wm * 32 + mt * 16 + g, r1 = r0 + 8;
                uint32_t o0 = chunk * H1_CHK + r0 * 64 + ((kin * 2) ^ ((r0 & 3) << 4));
                *(uint32_t*)(Hh + o0) =
                    pack2h(acc[mt][nt][0] + b1s[c0i], acc[mt][nt][1] + b1s[c0i + 1]);
                uint32_t o1 = chunk * H1_CHK + r1 * 64 + ((kin * 2) ^ ((r1 & 3) << 4));
                *(uint32_t*)(Hh + o1) =
                    pack2h(acc[mt][nt][2] + b1s[c0i], acc[mt][nt][3] + b1s[c0i + 1]);
            }
        }
    }
    __syncthreads();

    // ================== LAYER 2: D2[64x192] = H1 @ Wh[e]^T (sync-free) ==================
    const uint32_t h1row2 = (uint32_t)(wm * 32 + llow);
    const uint32_t h1sw2  = (h1row2 & 3) << 4;
    const uint32_t aH2    = sb + H1_OFF + h1row2 * 64;
    const uint4* __restrict__ whf = g_Whf4 + ((size_t)(e * 16) * 12 + wn * 3) * 32 + lane;

    float acc2[2][6][4];
    #pragma unroll
    for (int mt = 0; mt < 2; mt++)
        #pragma unroll
        for (int nt = 0; nt < 6; nt++)
            #pragma unroll
            for (int q = 0; q < 4; q++) acc2[mt][nt][q] = 0.f;

    uint4 wb[3];
    #pragma unroll
    for (int j = 0; j < 3; j++) wb[j] = __ldg(whf + j * 32);
    #pragma unroll 2
    for (int kc2 = 0; kc2 < 16; kc2++) {
        uint4 p[3];
        #pragma unroll
        for (int j = 0; j < 3; j++) p[j] = wb[j];
        if (kc2 + 1 < 16) {
            #pragma unroll
            for (int j = 0; j < 3; j++)
                wb[j] = __ldg(whf + (kc2 + 1) * 384 + j * 32);
        }
        const uint32_t colsw = (((kc2 & 1) << 5) + ahi16) ^ h1sw2;
        const uint32_t aH = aH2 + (kc2 >> 1) * H1_CHK + colsw;
        uint32_t ah0[4], ah1[4];
        ldm4(ah0, aH);
        ldm4(ah1, aH + 1024);
        #pragma unroll
        for (int j = 0; j < 3; j++) {
            mma_f16(acc2[0][2 * j],     ah0, p[j].x, p[j].y);
            mma_f16(acc2[1][2 * j],     ah1, p[j].x, p[j].y);
            mma_f16(acc2[0][2 * j + 1], ah0, p[j].z, p[j].w);
            mma_f16(acc2[1][2 * j + 1], ah1, p[j].z, p[j].w);
        }
    }

    // ---- fused epilogue: E = relu(D2 + bh) . W2 + b2, per-batch bins ----
    {
        const int C0 = wn * 48;
        const int R0 = wm * 32;
        float pv[2][2] = {{0.f, 0.f}, {0.f, 0.f}};
        #pragma unroll
        for (int mt = 0; mt < 2; mt++) {
            #pragma unroll
            for (int nt = 0; nt < 6; nt++) {
                int c0i = C0 + nt * 8 + 2 * t;
                float bb0 = bhs[c0i],     w0 = w2s[c0i];
                float bb1 = bhs[c0i + 1], w1v = w2s[c0i + 1];
                float v;
                v = acc2[mt][nt][0] + bb0; v = v > 0.f ? v : 0.f; pv[mt][0] = fmaf(v, w0,  pv[mt][0]);
                v = acc2[mt][nt][1] + bb1; v = v > 0.f ? v : 0.f; pv[mt][0] = fmaf(v, w1v, pv[mt][0]);
                v = acc2[mt][nt][2] + bb0; v = v > 0.f ? v : 0.f; pv[mt][1] = fmaf(v, w0,  pv[mt][1]);
                v = acc2[mt][nt][3] + bb1; v = v > 0.f ? v : 0.f; pv[mt][1] = fmaf(v, w1v, pv[mt][1]);
            }
        }
        #pragma unroll
        for (int mt = 0; mt < 2; mt++) {
            #pragma unroll
            for (int h = 0; h < 2; h++) {
                pv[mt][h] += __shfl_xor_sync(0xffffffffu, pv[mt][h], 1);
                pv[mt][h] += __shfl_xor_sync(0xffffffffu, pv[mt][h], 2);
            }
        }
        if (t == 0) {
            #pragma unroll
            for (int mt = 0; mt < 2; mt++) {
                red[R0 + mt * 16 + g][wn]     = pv[mt][0];
                red[R0 + mt * 16 + 8 + g][wn] = pv[mt][1];
            }
        }
        __syncthreads();
        if (tid < TM) {
            int pr = prow[tid];
            if (pr >= 0) {
                float en = red[tid][0] + red[tid][1] + red[tid][2] + red[tid][3] + b2[e];
                atomicAdd(&bins[pr >> 10], en);
            }
        }
        __syncthreads();
        if (tid < BB) {
            float v = bins[tid];
            if (v != 0.f) atomicAdd(&outp[tid], v);
        }
    }
}

extern "C" void kernel_launch(void* const* d_in, const int* in_sizes, int n_in,
                              void* d_out, int out_size) {
    const float* rep     = (const float*)d_in[0];
    const int*   species = (const int*)  d_in[1];
    const float* W1      = (const float*)d_in[2];
    const float* b1      = (const float*)d_in[3];
    const float* Wh      = (const float*)d_in[4];
    const float* bh      = (const float*)d_in[5];
    const float* W2      = (const float*)d_in[6];
    const float* b2      = (const float*)d_in[7];
    float* out = (float*)d_out;

    cudaFuncSetAttribute(fused_mlp,
                         cudaFuncAttributeMaxDynamicSharedMemorySize, DSMEM);

    void* cptr = nullptr;
    cudaGetSymbolAddress(&cptr, g_counts);
    cudaMemsetAsync(cptr, 0, EE * sizeof(int), 0);
    cudaMemsetAsync(out, 0, BB * sizeof(float), 0);
    const int FRAG = W1F4_N + WHF4_N;               // 73728
    bucket_prep_kernel<<<128 + (FRAG + 255) / 256, 256>>>(species, W1, Wh);
    fused_mlp<<<MAXTILES, NT, DSMEM>>>(rep, b1, bh, W2, b2, out);
}

// round 14
// speedup vs baseline: 1.1511x; 1.0826x over previous
#include <cuda_runtime.h>
#include <cuda_fp16.h>
#include <cstdint>

#define BB 32
#define AA 1024
#define DD 384
#define EE 4
#define H1C 256
#define H2C 192
#define NATOMS (BB*AA)
#define TM 64
#define NT 256
#define MAXTILES 516

// ---- dynamic SMEM byte map (per CTA) ----
#define A_CHK 5120           // 64 rows x 80B per k32 chunk
#define H1_OFF 61440
#define H1_CHK 4096          // 64 rows x 64B per k32 chunk
#define DSMEM 94208

// fragment-pair weights: [e][kc2][pair][lane] as uint4 {b0a,b1a,b0b,b1b}
#define W1F4_N (EE * 24 * 16 * 32)   // 49152
#define WHF4_N (EE * 16 * 12 * 32)   // 24576

// ---------------- device scratch ----------------
__device__ int   g_counts[EE];
__device__ int   g_perm[EE * NATOMS];
__device__ __align__(16) uint4 g_W1f4[W1F4_N];
__device__ __align__(16) uint4 g_Whf4[WHF4_N];

// ---------------- helpers ----------------
__device__ __forceinline__ uint32_t s2u(const void* p) {
    uint32_t a;
    asm("{ .reg .u64 t; cvta.to.shared.u64 t, %1; cvt.u32.u64 %0, t; }" : "=r"(a) : "l"(p));
    return a;
}

__device__ __forceinline__ uint32_t pack2h(float x0, float x1) {
    __half2 h = __floats2half2_rn(x0, x1);
    return *(uint32_t*)&h;
}

__device__ __forceinline__ void mma_f16(float* d,
        const uint32_t* a, uint32_t b0, uint32_t b1) {
    asm volatile(
        "mma.sync.aligned.m16n8k16.row.col.f32.f16.f16.f32 "
        "{%0,%1,%2,%3}, {%4,%5,%6,%7}, {%8,%9}, {%0,%1,%2,%3};"
        : "+f"(d[0]), "+f"(d[1]), "+f"(d[2]), "+f"(d[3])
        : "r"(a[0]), "r"(a[1]), "r"(a[2]), "r"(a[3]), "r"(b0), "r"(b1));
}

__device__ __forceinline__ void ldm4(uint32_t* r, uint32_t addr) {
    asm volatile("ldmatrix.sync.aligned.m8n8.x4.shared.b16 {%0,%1,%2,%3}, [%4];"
        : "=r"(r[0]), "=r"(r[1]), "=r"(r[2]), "=r"(r[3]) : "r"(addr));
}

// ---------------- setup: bucket (blocks 0..127) + fragment prep ----------------
__global__ void bucket_prep_kernel(const int* __restrict__ species,
                                   const float* __restrict__ W1,
                                   const float* __restrict__ Wh) {
    const int tid = threadIdx.x;
    const int b = blockIdx.x;
    if (b < 128) {
        int i = b * 256 + tid;
        int lane = tid & 31;
        int e = species[i];
        unsigned mask = __match_any_sync(0xffffffffu, e);
        int leader = __ffs(mask) - 1;
        int rank = __popc(mask & ((1u << lane) - 1u));
        int base = 0;
        if (lane == leader) base = atomicAdd(&g_counts[e], __popc(mask));
        base = __shfl_sync(0xffffffffu, base, leader);
        g_perm[e * NATOMS + base + rank] = i;
        return;
    }
    int idx = (b - 128) * 256 + tid;
    if (idx < W1F4_N) {
        int lane = idx & 31;
        int p8   = (idx >> 5) & 15;
        int rest = idx >> 9;
        int kc2  = rest % 24;
        int e    = rest / 24;
        int k = kc2 * 16 + 2 * (lane & 3);
        int n = p8 * 16 + (lane >> 2);
        const float* Wp = W1 + ((size_t)e * DD + k) * H1C + n;
        uint32_t b0a = pack2h(Wp[0],                Wp[H1C]);
        uint32_t b1a = pack2h(Wp[(size_t)8 * H1C],  Wp[(size_t)9 * H1C]);
        uint32_t b0b = pack2h(Wp[8],                Wp[H1C + 8]);
        uint32_t b1b = pack2h(Wp[(size_t)8 * H1C + 8], Wp[(size_t)9 * H1C + 8]);
        g_W1f4[idx] = make_uint4(b0a, b1a, b0b, b1b);
    } else if (idx < W1F4_N + WHF4_N) {
        int i2 = idx - W1F4_N;
        int lane = i2 & 31;
        int tmp  = i2 >> 5;
        int p8   = tmp % 12;
        int rest = tmp / 12;
        int kc2  = rest % 16;
        int e    = rest / 16;
        int k = kc2 * 16 + 2 * (lane & 3);
        int n = p8 * 16 + (lane >> 2);
        const float* Wp = Wh + ((size_t)e * H1C + k) * H2C + n;
        uint32_t b0a = pack2h(Wp[0],                Wp[H2C]);
        uint32_t b1a = pack2h(Wp[(size_t)8 * H2C],  Wp[(size_t)9 * H2C]);
        uint32_t b0b = pack2h(Wp[8],                Wp[H2C + 8]);
        uint32_t b1b = pack2h(Wp[(size_t)8 * H2C + 8], Wp[(size_t)9 * H2C + 8]);
        g_Whf4[i2] = make_uint4(b0a, b1a, b0b, b1b);
    }
}

// ---------------- fused 2-layer MLP + batch reduction (TM=64, 2 CTA/SM, full unroll) ----------------
__global__ void __launch_bounds__(NT, 2) fused_mlp(
    const float* __restrict__ rep,
    const float* __restrict__ b1, const float* __restrict__ bh,
    const float* __restrict__ W2, const float* __restrict__ b2,
    float* __restrict__ outp)
{
    extern __shared__ __align__(16) char dsm[];
    __shared__ int   prow[TM];
    __shared__ float b1s[H1C];
    __shared__ float bhs[H2C];
    __shared__ float w2s[H2C];
    __shared__ float red[TM][4];
    __shared__ float bins[BB];

    const int tid  = threadIdx.x;
    const int w    = tid >> 5;
    const int lane = tid & 31;
    const int g    = lane >> 2;
    const int t    = lane & 3;
    const int llow = lane & 15;
    const int ahi16 = (lane >> 4) << 4;

    const int wm = w >> 2;        // 0..1 -> 32-row slab
    const int wn = w & 3;         // 0..3 -> N quarter

    int c0 = g_counts[0], c1 = g_counts[1], c2 = g_counts[2], c3 = g_counts[3];
    int t0 = (c0 + TM - 1) / TM, t1 = (c1 + TM - 1) / TM;
    int t2 = (c2 + TM - 1) / TM, t3 = (c3 + TM - 1) / TM;
    int bid = blockIdx.x, e, tloc, cnt;
    if      (bid < t0)                { e = 0; tloc = bid;                cnt = c0; }
    else if (bid < t0 + t1)           { e = 1; tloc = bid - t0;           cnt = c1; }
    else if (bid < t0 + t1 + t2)      { e = 2; tloc = bid - t0 - t1;      cnt = c2; }
    else if (bid < t0 + t1 + t2 + t3) { e = 3; tloc = bid - t0 - t1 - t2; cnt = c3; }
    else return;

    const int row0   = tloc * TM;
    const int mcount = min(TM, cnt - row0);
    if (tid < TM)
        prow[tid] = (tid < mcount) ? g_perm[e * NATOMS + row0 + tid] : -1;
    b1s[tid] = b1[e * H1C + tid];
    if (tid < H2C) { bhs[tid] = bh[e * H2C + tid]; w2s[tid] = W2[e * H2C + tid]; }
    if (tid < BB) bins[tid] = 0.f;
    __syncthreads();

    const uint32_t sb = s2u(dsm);

    // ---- pack FULL A tile (64 x 384) fp16 into chunked smem, once (full unroll: batch loads) ----
    {
        int r = tid >> 2;
        int fq = tid & 3;
        int p = prow[r];
        const float4* src = (p >= 0) ? (const float4*)(rep + (size_t)p * DD) : nullptr;
        char* Arow = dsm + r * 80;
        #pragma unroll
        for (int c = 0; c < 12; c++) {
            #pragma unroll
            for (int j = 0; j < 2; j++) {
                int f = fq * 2 + j;
                float4 v = src ? __ldg(src + c * 8 + f) : make_float4(0.f, 0.f, 0.f, 0.f);
                *(uint2*)(Arow + c * A_CHK + f * 8) =
                    make_uint2(pack2h(v.x, v.y), pack2h(v.z, v.w));
            }
        }
    }
    __syncthreads();

    // ================== LAYER 1: D1[64x256] = A @ W1[e]^T (sync-free, full unroll) ==================
    const uint32_t aB1 = sb + (uint32_t)((wm * 32 + llow) * 80 + ahi16);
    const uint4* __restrict__ w1f = g_W1f4 + ((size_t)(e * 24) * 16 + wn * 4) * 32 + lane;

    float acc[2][8][4];
    #pragma unroll
    for (int mt = 0; mt < 2; mt++)
        #pragma unroll
        for (int nt = 0; nt < 8; nt++)
            #pragma unroll
            for (int q = 0; q < 4; q++) acc[mt][nt][q] = 0.f;

    #pragma unroll
    for (int kc2 = 0; kc2 < 24; kc2++) {
        uint4 bp[4];
        #pragma unroll
        for (int j = 0; j < 4; j++) bp[j] = __ldg(w1f + kc2 * 512 + j * 32);
        const uint32_t aB = aB1 + (kc2 >> 1) * A_CHK + (kc2 & 1) * 32;
        uint32_t af[2][4];
        ldm4(af[0], aB);
        ldm4(af[1], aB + 1280);
        #pragma unroll
        for (int j = 0; j < 4; j++) {
            #pragma unroll
            for (int mt = 0; mt < 2; mt++) {
                mma_f16(acc[mt][2 * j],     af[mt], bp[j].x, bp[j].y);
                mma_f16(acc[mt][2 * j + 1], af[mt], bp[j].z, bp[j].w);
            }
        }
    }

    // ---- H1 = D1 + b1 (NO relu — reference quirk) -> chunked swizzled smem ----
    {
        char* Hh = dsm + H1_OFF;
        #pragma unroll
        for (int mt = 0; mt < 2; mt++) {
            #pragma unroll
            for (int nt = 0; nt < 8; nt++) {
                int c0i = wn * 64 + nt * 8 + 2 * t;
                int chunk = c0i >> 5, kin = c0i & 31;
                int r0 = wm * 32 + mt * 16 + g, r1 = r0 + 8;
                uint32_t o0 = chunk * H1_CHK + r0 * 64 + ((kin * 2) ^ ((r0 & 3) << 4));
                *(uint32_t*)(Hh + o0) =
                    pack2h(acc[mt][nt][0] + b1s[c0i], acc[mt][nt][1] + b1s[c0i + 1]);
                uint32_t o1 = chunk * H1_CHK + r1 * 64 + ((kin * 2) ^ ((r1 & 3) << 4));
                *(uint32_t*)(Hh + o1) =
                    pack2h(acc[mt][nt][2] + b1s[c0i], acc[mt][nt][3] + b1s[c0i + 1]);
            }
        }
    }
    __syncthreads();

    // ================== LAYER 2: D2[64x192] = H1 @ Wh[e]^T (sync-free, full unroll) ==================
    const uint32_t h1row2 = (uint32_t)(wm * 32 + llow);
    const uint32_t h1sw2  = (h1row2 & 3) << 4;
    const uint32_t aH2    = sb + H1_OFF + h1row2 * 64;
    const uint4* __restrict__ whf = g_Whf4 + ((size_t)(e * 16) * 12 + wn * 3) * 32 + lane;

    float acc2[2][6][4];
    #pragma unroll
    for (int mt = 0; mt < 2; mt++)
        #pragma unroll
        for (int nt = 0; nt < 6; nt++)
            #pragma unroll
            for (int q = 0; q < 4; q++) acc2[mt][nt][q] = 0.f;

    #pragma unroll
    for (int kc2 = 0; kc2 < 16; kc2++) {
        uint4 p[3];
        #pragma unroll
        for (int j = 0; j < 3; j++) p[j] = __ldg(whf + kc2 * 384 + j * 32);
        const uint32_t colsw = (((kc2 & 1) << 5) + ahi16) ^ h1sw2;
        const uint32_t aH = aH2 + (kc2 >> 1) * H1_CHK + colsw;
        uint32_t ah0[4], ah1[4];
        ldm4(ah0, aH);
        ldm4(ah1, aH + 1024);
        #pragma unroll
        for (int j = 0; j < 3; j++) {
            mma_f16(acc2[0][2 * j],     ah0, p[j].x, p[j].y);
            mma_f16(acc2[1][2 * j],     ah1, p[j].x, p[j].y);
            mma_f16(acc2[0][2 * j + 1], ah0, p[j].z, p[j].w);
            mma_f16(acc2[1][2 * j + 1], ah1, p[j].z, p[j].w);
        }
    }

    // ---- fused epilogue: E = relu(D2 + bh) . W2 + b2, per-batch bins ----
    {
        const int C0 = wn * 48;
        const int R0 = wm * 32;
        float pv[2][2] = {{0.f, 0.f}, {0.f, 0.f}};
        #pragma unroll
        for (int mt = 0; mt < 2; mt++) {
            #pragma unroll
            for (int nt = 0; nt < 6; nt++) {
                int c0i = C0 + nt * 8 + 2 * t;
                float bb0 = bhs[c0i],     w0 = w2s[c0i];
                float bb1 = bhs[c0i + 1], w1v = w2s[c0i + 1];
                float v;
                v = acc2[mt][nt][0] + bb0; v = v > 0.f ? v : 0.f; pv[mt][0] = fmaf(v, w0,  pv[mt][0]);
                v = acc2[mt][nt][1] + bb1; v = v > 0.f ? v : 0.f; pv[mt][0] = fmaf(v, w1v, pv[mt][0]);
                v = acc2[mt][nt][2] + bb0; v = v > 0.f ? v : 0.f; pv[mt][1] = fmaf(v, w0,  pv[mt][1]);
                v = acc2[mt][nt][3] + bb1; v = v > 0.f ? v : 0.f; pv[mt][1] = fmaf(v, w1v, pv[mt][1]);
            }
        }
        #pragma unroll
        for (int mt = 0; mt < 2; mt++) {
            #pragma unroll
            for (int h = 0; h < 2; h++) {
                pv[mt][h] += __shfl_xor_sync(0xffffffffu, pv[mt][h], 1);
                pv[mt][h] += __shfl_xor_sync(0xffffffffu, pv[mt][h], 2);
            }
        }
        if (t == 0) {
            #pragma unroll
            for (int mt = 0; mt < 2; mt++) {
                red[R0 + mt * 16 + g][wn]     = pv[mt][0];
                red[R0 + mt * 16 + 8 + g][wn] = pv[mt][1];
            }
        }
        __syncthreads();
        if (tid < TM) {
            int pr = prow[tid];
            if (pr >= 0) {
                float en = red[tid][0] + red[tid][1] + red[tid][2] + red[tid][3] + b2[e];
                atomicAdd(&bins[pr >> 10], en);
            }
        }
        __syncthreads();
        if (tid < BB) {
            float v = bins[tid];
            if (v != 0.f) atomicAdd(&outp[tid], v);
        }
    }
}

extern "C" void kernel_launch(void* const* d_in, const int* in_sizes, int n_in,
                              void* d_out, int out_size) {
    const float* rep     = (const float*)d_in[0];
    const int*   species = (const int*)  d_in[1];
    const float* W1      = (const float*)d_in[2];
    const float* b1      = (const float*)d_in[3];
    const float* Wh      = (const float*)d_in[4];
    const float* bh      = (const float*)d_in[5];
    const float* W2      = (const float*)d_in[6];
    const float* b2      = (const float*)d_in[7];
    float* out = (float*)d_out;

    cudaFuncSetAttribute(fused_mlp,
                         cudaFuncAttributeMaxDynamicSharedMemorySize, DSMEM);

    void* cptr = nullptr;
    cudaGetSymbolAddress(&cptr, g_counts);
    cudaMemsetAsync(cptr, 0, EE * sizeof(int), 0);
    cudaMemsetAsync(out, 0, BB * sizeof(float), 0);
    const int FRAG = W1F4_N + WHF4_N;               // 73728
    bucket_prep_kernel<<<128 + (FRAG + 255) / 256, 256>>>(species, W1, Wh);
    fused_mlp<<<MAXTILES, NT, DSMEM>>>(rep, b1, bh, W2, b2, out);
}